// round 6
// baseline (speedup 1.0000x reference)
#include <cuda_runtime.h>
#include <cuda_fp16.h>
#include <cstdint>

#define BB 128          // batch
#define PP 1200         // feature dim
#define QH 960          // fp16-cache column extent (union of q-ranges after it0)
#define NPB (BB * PP)   // 153600
#define MAXCH 12        // max p-chunks per iteration

// Static scratch (no allocations allowed)
__device__ float g_h[NPB];               // h state (in-place updated)
__device__ float g_C[NPB];               // frozen-contribution cache C[b,q]
__device__ float g_partial[MAXCH * NPB]; // per-chunk partial sums [chunk][b][q]
// fp16 cache of M[:, :, 0:960], written during iter0, read by iters 1-4 (295 MB)
__device__ __align__(16) __half g_Mh[(size_t)BB * PP * QH];

__device__ __forceinline__ float f_p(float x) {
    float t = fminf(fmaxf(x, -1.0f), 1.0f);
    return t > 0.0f ? t : 0.01f * t;
}

// 16-byte streaming load as two packed f32x2 (64-bit) registers
struct U64x2 { unsigned long long a, b; };
__device__ __forceinline__ U64x2 ldg_cs_128(const void* p) {
    U64x2 r;
    asm("ld.global.cs.v2.u64 {%0,%1}, [%2];" : "=l"(r.a), "=l"(r.b) : "l"(p));
    return r;
}

// Packed dual-fp32 FMA: acc = m * hp + acc   (Blackwell f32x2 pipe)
#define FMA2(acc, m, hp) \
    asm("fma.rn.f32x2 %0, %1, %2, %0;" : "+l"(acc) : "l"(m), "l"(hp))

// ---------------------------------------------------------------------------
// iter-0 phase A (fp32 M): partial[ch][b][q] = sum_p f_p(query)[b,p]*M[b,p,q]
// Also emits the fp16 cache for q<QH while the fp32 data is in registers.
// ---------------------------------------------------------------------------
template<int PC>
__global__ void phaseA0(const float* __restrict__ M, const float* __restrict__ query)
{
    const int ch  = blockIdx.x;
    const int b   = blockIdx.y;
    const int tid = threadIdx.x;
    const int pbase = ch * PC;

    __shared__ float2 hd[PC];
    #pragma unroll
    for (int i = tid; i < PC; i += 128) {
        float v = f_p(query[b * PP + pbase + i]);
        hd[i] = make_float2(v, v);
    }
    __syncthreads();

    const int q0 = blockIdx.z * 512 + tid * 4;
    if (q0 >= PP) return;

    const char* base = (const char*)(M + (size_t)b * PP * PP
                                       + (size_t)pbase * PP + q0);
    const bool emit = (q0 < QH);
    char* mh = (char*)(g_Mh + ((size_t)b * PP + pbase) * QH + q0);

    unsigned long long acc0 = 0, acc1 = 0;

    #pragma unroll 8
    for (int p = 0; p < PC; ++p) {
        unsigned long long hp = *reinterpret_cast<const unsigned long long*>(&hd[p]);
        U64x2 m = ldg_cs_128(base + (size_t)p * (PP * 4));
        FMA2(acc0, m.a, hp);
        FMA2(acc1, m.b, hp);
        if (emit) {
            __half2 c01 = __float22half2_rn(*reinterpret_cast<float2*>(&m.a));
            __half2 c23 = __float22half2_rn(*reinterpret_cast<float2*>(&m.b));
            uint2 v;
            v.x = *reinterpret_cast<unsigned*>(&c01);
            v.y = *reinterpret_cast<unsigned*>(&c23);
            *reinterpret_cast<uint2*>(mh + (size_t)p * (QH * 2)) = v;
        }
    }

    unsigned long long* out = reinterpret_cast<unsigned long long*>(
        g_partial + ((size_t)ch * BB + b) * PP + q0);
    out[0] = acc0;
    out[1] = acc1;
}

// ---------------------------------------------------------------------------
// iters 1-4 phase A (fp16 M cache): thread owns 8 consecutive q
// (one LDG.128 = 8 halves per p). fp32 accumulate.
// ---------------------------------------------------------------------------
template<int PC>
__global__ void phaseA16(int non)
{
    const int ch  = blockIdx.x;
    const int b   = blockIdx.y;
    const int tid = threadIdx.x;
    const int pbase = ch * PC;

    __shared__ float hd[PC];
    for (int i = tid; i < PC; i += blockDim.x)
        hd[i] = g_h[b * PP + pbase + i];
    __syncthreads();

    const int q0 = tid * 8;
    if (q0 >= non) return;

    const char* base = (const char*)(g_Mh + ((size_t)b * PP + pbase) * QH + q0);

    float acc[8];
    #pragma unroll
    for (int k = 0; k < 8; ++k) acc[k] = 0.0f;

    #pragma unroll 4
    for (int p = 0; p < PC; ++p) {
        float h = hd[p];
        uint4 raw = __ldcs(reinterpret_cast<const uint4*>(base + (size_t)p * (QH * 2)));
        float2 f0 = __half22float2(*reinterpret_cast<__half2*>(&raw.x));
        float2 f1 = __half22float2(*reinterpret_cast<__half2*>(&raw.y));
        float2 f2 = __half22float2(*reinterpret_cast<__half2*>(&raw.z));
        float2 f3 = __half22float2(*reinterpret_cast<__half2*>(&raw.w));
        acc[0] = fmaf(h, f0.x, acc[0]);
        acc[1] = fmaf(h, f0.y, acc[1]);
        acc[2] = fmaf(h, f1.x, acc[2]);
        acc[3] = fmaf(h, f1.y, acc[3]);
        acc[4] = fmaf(h, f2.x, acc[4]);
        acc[5] = fmaf(h, f2.y, acc[5]);
        acc[6] = fmaf(h, f3.x, acc[6]);
        acc[7] = fmaf(h, f3.y, acc[7]);
    }

    float4* out = reinterpret_cast<float4*>(
        g_partial + ((size_t)ch * BB + b) * PP + q0);
    out[0] = make_float4(acc[0], acc[1], acc[2], acc[3]);
    out[1] = make_float4(acc[4], acc[5], acc[6], acc[7]);
}

// ---------------------------------------------------------------------------
// phase B (fully templated per iteration):
//   mv = [C] + sum(partials); h = f_p(h*(kappa+mv)) in place (q < NON);
//   fold newly-frozen chunk contributions into C (first fold writes, not adds).
//   Last iteration writes d_out (full range incl. frozen passthrough).
// ---------------------------------------------------------------------------
template<int NON, int NCH, int NACT, bool READC, bool WRITEC, bool FIRSTW,
         bool IT0, bool LAST>
__global__ void phaseB_k(float* __restrict__ out, const float* __restrict__ query)
{
    int i = blockIdx.x * blockDim.x + threadIdx.x;

    int b, q, gi;
    if (LAST) {
        if (i >= NPB) return;
        b = i / PP; q = i % PP; gi = i;
        if (q >= NON) { out[gi] = g_h[gi]; return; }
    } else {
        if (i >= BB * NON) return;
        b = i / NON; q = i % NON; gi = b * PP + q;
    }

    float h = IT0 ? f_p(query[gi]) : g_h[gi];

    float sa = 0.0f, sf = 0.0f;
    const float* pp = g_partial + (size_t)b * PP + q;
    #pragma unroll
    for (int s = 0; s < NCH; ++s) {
        float v = pp[(size_t)s * NPB];
        if (s < NACT) sa += v; else sf += v;
    }

    float c  = READC ? g_C[gi] : 0.0f;
    float mv = sa + sf + c;
    if (WRITEC) g_C[gi] = FIRSTW ? sf : (c + sf);

    float val = f_p(h * (0.8f + mv));
    if (LAST) out[gi] = val; else g_h[gi] = val;
}

// ---------------------------------------------------------------------------
extern "C" void kernel_launch(void* const* d_in, const int* in_sizes, int n_in,
                              void* d_out, int out_size)
{
    const float* query = (const float*)d_in[0];
    const float* M     = (const float*)d_in[1];
    float*       out   = (float*)d_out;

    // Iteration plan (prev = p-range read, non = active q/p range):
    //  it : prev  non  pc  nch nact   phaseA grid
    //  0  : 1200 1200 120  10  10     (10,128,3) x128  fp32 M, emits fp16 cache
    //  1  : 1200  960 120  10   8     (10,128,1) x128  fp16
    //  2  :  960  720 120   8   6     ( 8,128,1) x128  fp16
    //  3  :  720  480  60  12   8     (12,128,1) x64   fp16
    //  4  :  480  240  60   8   4     ( 8,128,1) x32   fp16

    // --- iter 0 (fp32 M read + fp16 cache emit) ---
    phaseA0<120><<<dim3(10, BB, 3), 128>>>(M, query);
    phaseB_k<1200, 10, 10, false, false, false, true,  false>
        <<<(BB * 1200 + 255) / 256, 256>>>(out, query);

    // --- iter 1 ---
    phaseA16<120><<<dim3(10, BB, 1), 128>>>(960);
    phaseB_k< 960, 10,  8, false, true,  true,  false, false>
        <<<(BB * 960 + 255) / 256, 256>>>(out, query);

    // --- iter 2 ---
    phaseA16<120><<<dim3( 8, BB, 1), 128>>>(720);
    phaseB_k< 720,  8,  6, true,  true,  false, false, false>
        <<<(BB * 720 + 255) / 256, 256>>>(out, query);

    // --- iter 3 ---
    phaseA16< 60><<<dim3(12, BB, 1),  64>>>(480);
    phaseB_k< 480, 12,  8, true,  true,  false, false, false>
        <<<(BB * 480 + 255) / 256, 256>>>(out, query);

    // --- iter 4 ---
    phaseA16< 60><<<dim3( 8, BB, 1),  32>>>(240);
    phaseB_k< 240,  8,  4, true,  false, false, false, true >
        <<<(NPB + 255) / 256, 256>>>(out, query);
}

// round 7
// speedup vs baseline: 1.0426x; 1.0426x over previous
#include <cuda_runtime.h>
#include <cstdint>

#define BB 128          // batch
#define PP 1200         // feature dim
#define NPB (BB * PP)   // 153600
#define MAXCH 12        // max p-chunks per iteration

// Static scratch (ping-pong everything to avoid same-launch read/write races)
__device__ float g_hA[NPB];               // h state buffer A
__device__ float g_hB[NPB];               // h state buffer B
__device__ float g_C0[NPB];               // frozen-contribution cache buffers
__device__ float g_C1[NPB];
__device__ float g_pA[MAXCH * NPB];       // partial sums ping
__device__ float g_pB[MAXCH * NPB];       // partial sums pong

__device__ __forceinline__ float f_p(float x) {
    float t = fminf(fmaxf(x, -1.0f), 1.0f);
    return t > 0.0f ? t : 0.01f * t;
}

// 16-byte streaming load as two packed f32x2 (64-bit) registers
struct U64x2 { unsigned long long a, b; };
__device__ __forceinline__ U64x2 ldg_cs_128(const void* p) {
    U64x2 r;
    asm("ld.global.cs.v2.u64 {%0,%1}, [%2];" : "=l"(r.a), "=l"(r.b) : "l"(p));
    return r;
}

// Packed dual-fp32 FMA: acc = m * hp + acc   (Blackwell f32x2 pipe)
#define FMA2(acc, m, hp) \
    asm("fma.rn.f32x2 %0, %1, %2, %0;" : "+l"(acc) : "l"(m), "l"(hp))

// ---------------------------------------------------------------------------
// mainloop body: partial_out[ch][b][q0..q0+3] = sum_{p in chunk} hd[p]*M[b,p,q]
// ---------------------------------------------------------------------------
template<int PC>
__device__ __forceinline__ void mainloopA(
    const float* __restrict__ M, const float2* hd, float* __restrict__ pout,
    int ch, int b, int q0)
{
    const char* base = (const char*)(M + (size_t)b * PP * PP
                                       + (size_t)(ch * PC) * PP + q0);
    unsigned long long acc0 = 0, acc1 = 0;
    #pragma unroll 8
    for (int p = 0; p < PC; ++p) {
        unsigned long long hp = *reinterpret_cast<const unsigned long long*>(&hd[p]);
        U64x2 m = ldg_cs_128(base + (size_t)p * (PP * 4));
        FMA2(acc0, m.a, hp);
        FMA2(acc1, m.b, hp);
    }
    unsigned long long* out = reinterpret_cast<unsigned long long*>(
        pout + ((size_t)ch * BB + b) * PP + q0);
    out[0] = acc0;
    out[1] = acc1;
}

// ---------------------------------------------------------------------------
// iter-0 phase A: h = f_p(query); partials(0) -> pA
// ---------------------------------------------------------------------------
template<int PC>
__global__ void phaseA0(const float* __restrict__ M, const float* __restrict__ query)
{
    const int ch = blockIdx.x, b = blockIdx.y, tid = threadIdx.x;
    __shared__ float2 hd[PC];
    if (tid < PC) {
        float v = f_p(query[b * PP + ch * PC + tid]);
        hd[tid] = make_float2(v, v);
    }
    __syncthreads();
    const int q0 = blockIdx.z * (blockDim.x * 4) + tid * 4;
    if (q0 >= PP) return;
    mainloopA<PC>(M, hd, g_pA, ch, b, q0);
}

// ---------------------------------------------------------------------------
// fused kernel F_t:
//   prologue: h_t[window] = f_p(h_{t-1}*(0.8 + C_in + sum partials_in)) ;
//             z==0 block persists h_t and folds newly-frozen chunks into C_out.
//   mainloop: partials_t[own chunk] over q < n_on  -> partials_out
// Buffer ping-pong across launches removes all same-launch races.
// ---------------------------------------------------------------------------
template<int PC, int NCHP, int NACTP, bool READC, bool WRITEC, bool FIRSTW, bool IT0P>
__global__ void phaseF(const float* __restrict__ M,
                       const float* __restrict__ hin, float* __restrict__ hout,
                       const float* __restrict__ Cin, float* __restrict__ Cout,
                       const float* __restrict__ pin, float* __restrict__ pout,
                       int n_on)
{
    const int ch = blockIdx.x, b = blockIdx.y, tid = threadIdx.x;
    const int pbase = ch * PC;
    __shared__ float2 hd[PC];

    if (tid < PC) {
        const int q  = pbase + tid;
        const int gi = b * PP + q;
        float h = hin[gi];
        if (IT0P) h = f_p(h);

        float sa = 0.0f, sf = 0.0f;
        const float* pp = pin + (size_t)b * PP + q;
        #pragma unroll
        for (int s = 0; s < NCHP; ++s) {
            float v = pp[(size_t)s * NPB];
            if (s < NACTP) sa += v; else sf += v;
        }
        float c = READC ? Cin[gi] : 0.0f;
        float hnew = f_p(h * (0.8f + sa + sf + c));
        hd[tid] = make_float2(hnew, hnew);

        if (blockIdx.z == 0) {
            hout[gi] = hnew;
            if (WRITEC) Cout[gi] = FIRSTW ? sf : (c + sf);
        }
    }
    __syncthreads();

    const int q0 = blockIdx.z * (blockDim.x * 4) + tid * 4;
    if (q0 >= n_on) return;
    mainloopA<PC>(M, hd, pout, ch, b, q0);
}

// ---------------------------------------------------------------------------
// final update: out[q<240] = f_p(hB*(0.8 + C0 + sum of 8 chunks of pA));
// frozen passthrough selects the buffer that last wrote each q-range:
//   [240,480)->hB, [480,720)->hA, [720,960)->hB, [960,1200)->hA
// ---------------------------------------------------------------------------
__global__ void phaseBfinal(float* __restrict__ out)
{
    int i = blockIdx.x * blockDim.x + threadIdx.x;
    if (i >= NPB) return;
    int b = i / PP, q = i % PP;

    if (q >= 240) {
        bool useB = (q < 480) || (q >= 720 && q < 960);
        out[i] = useB ? g_hB[i] : g_hA[i];
        return;
    }

    float sa = 0.0f;
    const float* pp = g_pA + (size_t)b * PP + q;
    #pragma unroll
    for (int s = 0; s < 8; ++s) sa += pp[(size_t)s * NPB];

    float h = g_hB[i];
    out[i] = f_p(h * (0.8f + sa + g_C0[i]));
}

// ---------------------------------------------------------------------------
extern "C" void kernel_launch(void* const* d_in, const int* in_sizes, int n_in,
                              void* d_out, int out_size)
{
    const float* query = (const float*)d_in[0];
    const float* M     = (const float*)d_in[1];
    float*       out   = (float*)d_out;

    float *hA, *hB, *C0, *C1, *pA, *pB;
    cudaGetSymbolAddress((void**)&hA, g_hA);
    cudaGetSymbolAddress((void**)&hB, g_hB);
    cudaGetSymbolAddress((void**)&C0, g_C0);
    cudaGetSymbolAddress((void**)&C1, g_C1);
    cudaGetSymbolAddress((void**)&pA, g_pA);
    cudaGetSymbolAddress((void**)&pB, g_pB);

    // Plan (step t updates q<non_t, mainloop covers p<non_{t-1}):
    //  launch : pc nch  p-range  q-range  prologue(NCHP,NACTP)  h: in->out  C         partials
    //  A0     : 120 10  <1200    <1200    -                     query       -         ->pA
    //  F1     : 120 10  <1200    <960     (10,10) no C          query->hA   -         pA->pB
    //  F2     : 120  8  <960     <720     (10, 8) wC0 first     hA->hB      ->C0      pB->pA
    //  F3     :  60 12  <720     <480     ( 8, 6) rC0 wC1       hB->hA      C0->C1    pA->pB
    //  F4     :  60  8  <480     <240     (12, 8) rC1 wC0       hA->hB      C1->C0    pB->pA
    //  Bfinal : update q<240 from hB,C0,pA(8 chunks); frozen passthrough

    phaseA0<120><<<dim3(10, BB, 3), 128>>>(M, query);

    phaseF<120, 10, 10, false, false, false, true >
        <<<dim3(10, BB, 2), 128>>>(M, query, hA, C0, C1, pA, pB, 960);

    phaseF<120, 10,  8, false, true,  true,  false>
        <<<dim3( 8, BB, 2), 128>>>(M, hA, hB, C1, C0, pB, pA, 720);

    phaseF< 60,  8,  6, true,  true,  false, false>
        <<<dim3(12, BB, 1), 128>>>(M, hB, hA, C0, C1, pA, pB, 480);

    phaseF< 60, 12,  8, true,  true,  false, false>
        <<<dim3( 8, BB, 1),  64>>>(M, hA, hB, C1, C0, pB, pA, 240);

    phaseBfinal<<<(NPB + 255) / 256, 256>>>(out);
}

// round 8
// speedup vs baseline: 1.0625x; 1.0190x over previous
#include <cuda_runtime.h>
#include <cstdint>

#define BB 128          // batch
#define PP 1200         // feature dim
#define NPB (BB * PP)   // 153600
#define MAXCH 12        // max p-chunks per iteration

// Static scratch (ping-pong everything to avoid same-launch read/write races)
__device__ float g_hA[NPB];               // h state buffer A
__device__ float g_hB[NPB];               // h state buffer B
__device__ float g_C0[NPB];               // frozen-contribution cache buffers
__device__ float g_C1[NPB];
__device__ float g_pA[MAXCH * NPB];       // partial sums ping
__device__ float g_pB[MAXCH * NPB];       // partial sums pong

__device__ __forceinline__ float f_p(float x) {
    float t = fminf(fmaxf(x, -1.0f), 1.0f);
    return t > 0.0f ? t : 0.01f * t;
}

// streaming loads as packed f32x2 (64-bit) registers
struct U64x2 { unsigned long long a, b; };
__device__ __forceinline__ U64x2 ldg_cs_128(const void* p) {
    U64x2 r;
    asm("ld.global.cs.v2.u64 {%0,%1}, [%2];" : "=l"(r.a), "=l"(r.b) : "l"(p));
    return r;
}
__device__ __forceinline__ unsigned long long ldg_cs_64(const void* p) {
    unsigned long long r;
    asm("ld.global.cs.u64 %0, [%1];" : "=l"(r) : "l"(p));
    return r;
}

// Packed dual-fp32 FMA: acc = m * hp + acc   (Blackwell f32x2 pipe)
#define FMA2(acc, m, hp) \
    asm("fma.rn.f32x2 %0, %1, %2, %0;" : "+l"(acc) : "l"(m), "l"(hp))

// ---------------------------------------------------------------------------
// mainloop: partial_out[ch][b][q0..q0+QPT-1] = sum_{p in chunk} hd[p]*M[b,p,q]
// QPT = floats of q per thread (4 -> one LDG.128/p, 2 -> one LDG.64/p)
// ---------------------------------------------------------------------------
template<int PC, int QPT>
__device__ __forceinline__ void mainloopA(
    const float* __restrict__ M, const float2* hd, float* __restrict__ pout,
    int ch, int b, int q0)
{
    const char* base = (const char*)(M + (size_t)b * PP * PP
                                       + (size_t)(ch * PC) * PP + q0);
    if (QPT == 4) {
        unsigned long long acc0 = 0, acc1 = 0;
        #pragma unroll 8
        for (int p = 0; p < PC; ++p) {
            unsigned long long hp = *reinterpret_cast<const unsigned long long*>(&hd[p]);
            U64x2 m = ldg_cs_128(base + (size_t)p * (PP * 4));
            FMA2(acc0, m.a, hp);
            FMA2(acc1, m.b, hp);
        }
        unsigned long long* out = reinterpret_cast<unsigned long long*>(
            pout + ((size_t)ch * BB + b) * PP + q0);
        out[0] = acc0;
        out[1] = acc1;
    } else {
        unsigned long long acc0 = 0;
        #pragma unroll 8
        for (int p = 0; p < PC; ++p) {
            unsigned long long hp = *reinterpret_cast<const unsigned long long*>(&hd[p]);
            unsigned long long m = ldg_cs_64(base + (size_t)p * (PP * 4));
            FMA2(acc0, m, hp);
        }
        *reinterpret_cast<unsigned long long*>(
            pout + ((size_t)ch * BB + b) * PP + q0) = acc0;
    }
}

// ---------------------------------------------------------------------------
// iter-0 phase A: h = f_p(query); partials(0) -> pA
// ---------------------------------------------------------------------------
template<int PC>
__global__ void phaseA0(const float* __restrict__ M, const float* __restrict__ query)
{
    const int ch = blockIdx.x, b = blockIdx.y, tid = threadIdx.x;
    __shared__ float2 hd[PC];
    if (tid < PC) {
        float v = f_p(query[b * PP + ch * PC + tid]);
        hd[tid] = make_float2(v, v);
    }
    __syncthreads();
    const int q0 = blockIdx.z * (blockDim.x * 4) + tid * 4;
    if (q0 >= PP) return;
    mainloopA<PC, 4>(M, hd, g_pA, ch, b, q0);
}

// ---------------------------------------------------------------------------
// fused kernel F_t:
//   prologue: h_t[window] = f_p(h_{t-1}*(0.8 + C_in + sum partials_in)) ;
//             z==0 block persists h_t and folds newly-frozen chunks into C_out.
//   mainloop: partials_t[own chunk] over q < n_on  -> partials_out
// Buffer ping-pong across launches removes all same-launch races.
// ---------------------------------------------------------------------------
template<int PC, int QPT, int NCHP, int NACTP,
         bool READC, bool WRITEC, bool FIRSTW, bool IT0P>
__global__ void phaseF(const float* __restrict__ M,
                       const float* __restrict__ hin, float* __restrict__ hout,
                       const float* __restrict__ Cin, float* __restrict__ Cout,
                       const float* __restrict__ pin, float* __restrict__ pout,
                       int n_on)
{
    const int ch = blockIdx.x, b = blockIdx.y, tid = threadIdx.x;
    const int pbase = ch * PC;
    __shared__ float2 hd[PC];

    if (tid < PC) {
        const int q  = pbase + tid;
        const int gi = b * PP + q;
        float h = hin[gi];
        if (IT0P) h = f_p(h);

        float sa = 0.0f, sf = 0.0f;
        const float* pp = pin + (size_t)b * PP + q;
        #pragma unroll
        for (int s = 0; s < NCHP; ++s) {
            float v = pp[(size_t)s * NPB];
            if (s < NACTP) sa += v; else sf += v;
        }
        float c = READC ? Cin[gi] : 0.0f;
        float hnew = f_p(h * (0.8f + sa + sf + c));
        hd[tid] = make_float2(hnew, hnew);

        if (blockIdx.z == 0) {
            hout[gi] = hnew;
            if (WRITEC) Cout[gi] = FIRSTW ? sf : (c + sf);
        }
    }
    __syncthreads();

    const int q0 = blockIdx.z * (blockDim.x * QPT) + tid * QPT;
    if (q0 >= n_on) return;
    mainloopA<PC, QPT>(M, hd, pout, ch, b, q0);
}

// ---------------------------------------------------------------------------
// final update (float4-vectorized): out[q<240] = f_p(hB*(0.8 + C0 + sum of
// 8 chunks of pA)); frozen passthrough selects the buffer that last wrote
// each q-range: [240,480)->hB, [480,720)->hA, [720,960)->hB, [960,1200)->hA
// All region boundaries are multiples of 4, so each float4 group is uniform.
// ---------------------------------------------------------------------------
__global__ void phaseBfinal(float4* __restrict__ out)
{
    int i4 = blockIdx.x * blockDim.x + threadIdx.x;
    if (i4 >= NPB / 4) return;
    const int QG = PP / 4;            // 300 float4 groups per row
    int b = i4 / QG, r = i4 % QG;
    int q = r * 4;
    int gi4 = (b * PP + q) / 4;

    const float4* hA4 = reinterpret_cast<const float4*>(g_hA);
    const float4* hB4 = reinterpret_cast<const float4*>(g_hB);

    if (q >= 240) {
        bool useB = (q < 480) || (q >= 720 && q < 960);
        out[i4] = useB ? hB4[gi4] : hA4[gi4];
        return;
    }

    float4 s = make_float4(0.f, 0.f, 0.f, 0.f);
    const float* pp = g_pA + (size_t)b * PP + q;
    #pragma unroll
    for (int sI = 0; sI < 8; ++sI) {
        float4 v = *reinterpret_cast<const float4*>(pp + (size_t)sI * NPB);
        s.x += v.x; s.y += v.y; s.z += v.z; s.w += v.w;
    }

    float4 h = hB4[gi4];
    float4 c = reinterpret_cast<const float4*>(g_C0)[gi4];
    float4 o;
    o.x = f_p(h.x * (0.8f + s.x + c.x));
    o.y = f_p(h.y * (0.8f + s.y + c.y));
    o.z = f_p(h.z * (0.8f + s.z + c.z));
    o.w = f_p(h.w * (0.8f + s.w + c.w));
    out[i4] = o;
}

// ---------------------------------------------------------------------------
extern "C" void kernel_launch(void* const* d_in, const int* in_sizes, int n_in,
                              void* d_out, int out_size)
{
    const float* query = (const float*)d_in[0];
    const float* M     = (const float*)d_in[1];
    float4*      out   = (float4*)d_out;

    float *hA, *hB, *C0, *C1, *pA, *pB;
    cudaGetSymbolAddress((void**)&hA, g_hA);
    cudaGetSymbolAddress((void**)&hB, g_hB);
    cudaGetSymbolAddress((void**)&C0, g_C0);
    cudaGetSymbolAddress((void**)&C1, g_C1);
    cudaGetSymbolAddress((void**)&pA, g_pA);
    cudaGetSymbolAddress((void**)&pB, g_pB);

    // Plan (step t updates q<non_t, mainloop covers p<non_{t-1}):
    //  launch : pc qpt nch  p-range  q-range  prologue(NCHP,NACTP)  h         C        partials
    //  A0     : 120  4  10  <1200    <1200    -                     query     -        ->pA
    //  F1     : 120  4  10  <1200    <960     (10,10) no C          query->hA -        pA->pB
    //  F2     : 120  4   8  <960     <720     (10, 8) wC0 first     hA->hB    ->C0     pB->pA
    //  F3     :  60  2  12  <720     <480     ( 8, 6) rC0 wC1       hB->hA    C0->C1   pA->pB
    //  F4     :  60  2   8  <480     <240     (12, 8) rC1 wC0       hA->hB    C1->C0   pB->pA
    //  Bfinal : update q<240 from hB,C0,pA(8 chunks); frozen passthrough

    phaseA0<120><<<dim3(10, BB, 3), 128>>>(M, query);

    phaseF<120, 4, 10, 10, false, false, false, true >
        <<<dim3(10, BB, 2), 128>>>(M, query, hA, C0, C1, pA, pB, 960);

    phaseF<120, 4, 10,  8, false, true,  true,  false>
        <<<dim3( 8, BB, 2), 128>>>(M, hA, hB, C1, C0, pB, pA, 720);

    phaseF< 60, 2,  8,  6, true,  true,  false, false>
        <<<dim3(12, BB, 1), 256>>>(M, hB, hA, C0, C1, pA, pB, 480);

    phaseF< 60, 2, 12,  8, true,  true,  false, false>
        <<<dim3( 8, BB, 1), 128>>>(M, hA, hB, C1, C0, pB, pA, 240);

    phaseBfinal<<<(NPB / 4 + 255) / 256, 256>>>(out);
}